// round 11
// baseline (speedup 1.0000x reference)
#include <cuda_runtime.h>
#include <cuda_fp16.h>

#define B_   4
#define LQ_  128
#define LK_  256
#define D_   128
#define H_   128
#define NH_  8

#define L2E 1.4426950408889634f  // log2(e) for softmax exp

#define NSPLIT 8                 // K-splits for the output projection

// ---- scratch (static device memory; no allocation) ----
__device__ __align__(16) __half g_KHh[B_*NH_*H_*LK_];     // [b][n][h][k] fp16
__device__ __align__(16) float  g_CONCAT[B_*LQ_*NH_*D_];  // [b][q][n*D+d]
__device__ __align__(16) float  g_PART[NSPLIT*B_*LQ_*H_]; // split-K partials

// ============================================================================
// K1: K-only per-head projection (Q-proj is fused into score_av).
// g_KHh[b][n][h][k] = (half) sum_d Wk[n][h][d] * K[b][k][d]
// 64x64 tile, BK=16, 256 threads, 4x4 per thread. grid (4, 2, 32).
// ============================================================================
__global__ void __launch_bounds__(256) kproj_kernel(
    const float* __restrict__ K, const float* __restrict__ Wk)
{
    int bn = blockIdx.z;
    int b = bn >> 3, n = bn & 7;
    int l0 = blockIdx.x * 64;

    __shared__ float Ws[16][64];   // [d][h]
    __shared__ float Xs[16][64];   // [d][l]
    int h0 = blockIdx.y * 64;
    int tid = threadIdx.x;                 // 256
    int ty = tid >> 4, tx = tid & 15;      // 16x16
    float acc[4][4] = {};
    const float* Wp = Wk + (n*H_ + h0)*D_;
    const float* Xp = K  + (b*LK_ + l0)*D_;
    int row = tid >> 2;          // 0..63
    int dq  = (tid & 3) * 4;     // 0,4,8,12
    for (int d0 = 0; d0 < D_; d0 += 16) {
        float4 w4 = *(const float4*)(Wp + row*D_ + d0 + dq);
        float4 x4 = *(const float4*)(Xp + row*D_ + d0 + dq);
        __syncthreads();
        Ws[dq+0][row] = w4.x; Ws[dq+1][row] = w4.y; Ws[dq+2][row] = w4.z; Ws[dq+3][row] = w4.w;
        Xs[dq+0][row] = x4.x; Xs[dq+1][row] = x4.y; Xs[dq+2][row] = x4.z; Xs[dq+3][row] = x4.w;
        __syncthreads();
        #pragma unroll
        for (int dd = 0; dd < 16; ++dd) {
            float4 a4 = *(const float4*)&Ws[dd][ty*4];
            float4 b4 = *(const float4*)&Xs[dd][tx*4];
            float av[4] = {a4.x, a4.y, a4.z, a4.w};
            float bv[4] = {b4.x, b4.y, b4.z, b4.w};
            #pragma unroll
            for (int i = 0; i < 4; ++i)
                #pragma unroll
                for (int j = 0; j < 4; ++j)
                    acc[i][j] = fmaf(av[i], bv[j], acc[i][j]);
        }
    }
    __half* Op = g_KHh + ((b*NH_ + n)*H_ + h0 + ty*4)*LK_ + l0 + tx*4;
    #pragma unroll
    for (int i = 0; i < 4; ++i) {
        __half2 h01 = __floats2half2_rn(acc[i][0], acc[i][1]);
        __half2 h23 = __floats2half2_rn(acc[i][2], acc[i][3]);
        *(__half2*)(Op + i*LK_)     = h01;
        *(__half2*)(Op + i*LK_ + 2) = h23;
    }
}

// ============================================================================
// K2: FUSED q-projection + scores + masked softmax + attn@V.
// Block = (b, n, 8 q-rows); grid (16, NH, B) = 512 blocks, 256 threads.
// Phase 0: compute qh for the 8 q rows in-block; keep as fp16 in smem
//          (identical rounding to the previous per-use cvt).
// Phase 1: thread = 4q x 2k; Ks double-buffered (1 sync/chunk, LDG overlapped).
// Phase 2: thread = 1q x 4d; Vs double-buffered 16-row chunks.
// k >= valid_len contributes exactly 0 (softmax mask).
// ============================================================================
__global__ void __launch_bounds__(256) score_av_kernel(
    const float* __restrict__ Q, const float* __restrict__ Wq,
    const float* __restrict__ wv, const int* __restrict__ valid_lens,
    const float* __restrict__ V)
{
    __shared__ float  Qin[8][D_];        // 4KB  input Q rows
    __shared__ __half Qs[H_][8];         // 2KB  qh fp16 [h][q]
    __shared__ float  wvs[H_];           // 0.5KB
    __shared__ __half Ks[2][16][LK_];    // 16KB double-buffered
    __shared__ float  attn_s[8][LK_];    // 8KB
    __shared__ float  Vs[2][16][D_];     // 16KB double-buffered
    __shared__ float  redA[2][4][4];
    __shared__ float  redB[2][4][4];

    int b = blockIdx.z, n = blockIdx.y;
    int q0 = blockIdx.x * 8;
    int tid = threadIdx.x;
    int valid = valid_lens[b];

    // ---- stage Q rows + wv ----
    {
        int r = tid >> 5, c4 = tid & 31;
        *(float4*)&Qin[r][c4*4] = *(const float4*)(Q + (b*LQ_ + q0 + r)*D_ + c4*4);
    }
    if (tid < 128) wvs[tid] = wv[n*H_ + tid];
    __syncthreads();

    // ---- Phase 0: q-projection. thread -> (h = tid>>1, 4 q's) ----
    {
        int h = tid >> 1, qq = (tid & 1) * 4;
        const float* Wrow = Wq + (n*H_ + h)*D_;
        float a0 = 0.f, a1 = 0.f, a2 = 0.f, a3 = 0.f;
        #pragma unroll 4
        for (int d = 0; d < D_; d += 4) {
            float4 w = *(const float4*)(Wrow + d);
            float4 x0 = *(const float4*)&Qin[qq+0][d];
            float4 x1 = *(const float4*)&Qin[qq+1][d];
            float4 x2 = *(const float4*)&Qin[qq+2][d];
            float4 x3 = *(const float4*)&Qin[qq+3][d];
            a0 = fmaf(w.x, x0.x, fmaf(w.y, x0.y, fmaf(w.z, x0.z, fmaf(w.w, x0.w, a0))));
            a1 = fmaf(w.x, x1.x, fmaf(w.y, x1.y, fmaf(w.z, x1.z, fmaf(w.w, x1.w, a1))));
            a2 = fmaf(w.x, x2.x, fmaf(w.y, x2.y, fmaf(w.z, x2.z, fmaf(w.w, x2.w, a2))));
            a3 = fmaf(w.x, x3.x, fmaf(w.y, x3.y, fmaf(w.z, x3.z, fmaf(w.w, x3.w, a3))));
        }
        Qs[h][qq+0] = __float2half(a0);
        Qs[h][qq+1] = __float2half(a1);
        Qs[h][qq+2] = __float2half(a2);
        Qs[h][qq+3] = __float2half(a3);
    }
    // (Qs reads happen after the first in-loop __syncthreads below)

    // ---- Phase 1: scores, Ks double-buffered ----
    int qg = tid >> 7;      // 0..1
    int kg = tid & 127;     // 0..127
    int ks = kg * 2;
    bool active = ks < valid;
    const __half* KHp = g_KHh + ((b*NH_ + n)*H_)*LK_;
    int srow = tid >> 5;              // 0..7 staging row (and +8)
    int scol = (tid & 31) * 8;        // halves, 16B aligned
    float acc[4][2] = {};

    uint4 ra = *(const uint4*)(KHp + srow*LK_ + scol);
    uint4 rb = *(const uint4*)(KHp + (srow+8)*LK_ + scol);
    #pragma unroll
    for (int c = 0; c < 8; ++c) {
        int buf = c & 1;
        *(uint4*)&Ks[buf][srow][scol]   = ra;
        *(uint4*)&Ks[buf][srow+8][scol] = rb;
        if (c < 7) {
            const __half* src = KHp + (c+1)*16*LK_;
            ra = *(const uint4*)(src + srow*LK_ + scol);
            rb = *(const uint4*)(src + (srow+8)*LK_ + scol);
        }
        __syncthreads();
        if (active) {
            int h0 = c * 16;
            #pragma unroll
            for (int dd = 0; dd < 16; ++dd) {
                unsigned k2u = *(const unsigned*)&Ks[buf][dd][ks];
                unsigned q01 = *(const unsigned*)&Qs[h0+dd][qg*4];
                unsigned q23 = *(const unsigned*)&Qs[h0+dd][qg*4+2];
                float w = wvs[h0+dd];
                unsigned bq0, bq1, bq2, bq3;
                asm("prmt.b32 %0, %1, %1, 0x1010;" : "=r"(bq0) : "r"(q01));
                asm("prmt.b32 %0, %1, %1, 0x3232;" : "=r"(bq1) : "r"(q01));
                asm("prmt.b32 %0, %1, %1, 0x1010;" : "=r"(bq2) : "r"(q23));
                asm("prmt.b32 %0, %1, %1, 0x3232;" : "=r"(bq3) : "r"(q23));
                unsigned bqs[4] = {bq0, bq1, bq2, bq3};
                #pragma unroll
                for (int i = 0; i < 4; ++i) {
                    unsigned su, tu;
                    asm("add.rn.f16x2 %0, %1, %2;"  : "=r"(su) : "r"(bqs[i]), "r"(k2u));
                    asm("tanh.approx.f16x2 %0, %1;" : "=r"(tu) : "r"(su));
                    float2 f = __half22float2(*reinterpret_cast<__half2*>(&tu));
                    acc[i][0] = fmaf(w, f.x, acc[i][0]);
                    acc[i][1] = fmaf(w, f.y, acc[i][1]);
                }
            }
        }
    }

    // ---- softmax over k (4 warps per q-group) ----
    float m[4];
    #pragma unroll
    for (int i = 0; i < 4; ++i) {
        float mm = -1e30f;
        #pragma unroll
        for (int j = 0; j < 2; ++j)
            if (ks + j < valid) mm = fmaxf(mm, acc[i][j]);
        m[i] = mm;
    }
    #pragma unroll
    for (int off = 16; off; off >>= 1)
        #pragma unroll
        for (int i = 0; i < 4; ++i)
            m[i] = fmaxf(m[i], __shfl_xor_sync(0xffffffffu, m[i], off));
    int w4 = (tid >> 5) & 3;
    if ((tid & 31) == 0)
        #pragma unroll
        for (int i = 0; i < 4; ++i) redA[qg][w4][i] = m[i];
    __syncthreads();
    #pragma unroll
    for (int i = 0; i < 4; ++i)
        m[i] = fmaxf(fmaxf(redA[qg][0][i], redA[qg][1][i]),
                     fmaxf(redA[qg][2][i], redA[qg][3][i]));

    float p[4][2], s[4] = {0.f, 0.f, 0.f, 0.f};
    #pragma unroll
    for (int i = 0; i < 4; ++i)
        #pragma unroll
        for (int j = 0; j < 2; ++j) {
            float e;
            asm("ex2.approx.f32 %0, %1;" : "=f"(e) : "f"((acc[i][j] - m[i]) * L2E));
            bool v = (ks + j) < valid;
            p[i][j] = v ? e : 0.0f;
            s[i] += p[i][j];
        }
    #pragma unroll
    for (int off = 16; off; off >>= 1)
        #pragma unroll
        for (int i = 0; i < 4; ++i)
            s[i] += __shfl_xor_sync(0xffffffffu, s[i], off);
    if ((tid & 31) == 0)
        #pragma unroll
        for (int i = 0; i < 4; ++i) redB[qg][w4][i] = s[i];
    __syncthreads();

    #pragma unroll
    for (int i = 0; i < 4; ++i) {
        float inv = 1.0f / (redB[qg][0][i] + redB[qg][1][i] +
                            redB[qg][2][i] + redB[qg][3][i]);
        *(float2*)&attn_s[qg*4+i][ks] = make_float2(p[i][0]*inv, p[i][1]*inv);
    }
    // (attn_s fully written for k in [0,256): zeros beyond valid)

    // ---- Phase 2: out = attn_s @ V[b], Vs double-buffered 16-row chunks ----
    int ty = tid >> 5;          // q row 0..7
    int tx = tid & 31;          // d group of 4
    float oa[4] = {};
    int nch = (valid + 15) >> 4;
    const float* Vp = V + (b*LK_)*D_;
    int vcol = (tid & 31) * 4;

    float4 va = *(const float4*)(Vp + srow*D_ + vcol);
    float4 vb = *(const float4*)(Vp + (srow+8)*D_ + vcol);
    for (int c = 0; c < nch; ++c) {
        int buf = c & 1;
        *(float4*)&Vs[buf][srow][vcol]   = va;
        *(float4*)&Vs[buf][srow+8][vcol] = vb;
        if (c + 1 < 16) {                 // bounds-safe prefetch (V has 256 rows)
            const float* src = Vp + (c+1)*16*D_;
            va = *(const float4*)(src + srow*D_ + vcol);
            vb = *(const float4*)(src + (srow+8)*D_ + vcol);
        }
        __syncthreads();                  // first iter also orders attn_s writes
        int k0 = c * 16;
        #pragma unroll
        for (int kk = 0; kk < 16; ++kk) {
            float a = attn_s[ty][k0+kk];  // broadcast within warp
            float4 v4 = *(const float4*)&Vs[buf][kk][tx*4];
            oa[0] = fmaf(a, v4.x, oa[0]);
            oa[1] = fmaf(a, v4.y, oa[1]);
            oa[2] = fmaf(a, v4.z, oa[2]);
            oa[3] = fmaf(a, v4.w, oa[3]);
        }
    }
    float* Cp = g_CONCAT + (b*LQ_ + q0 + ty)*(NH_*D_) + n*D_ + tx*4;
    *(float4*)Cp = make_float4(oa[0], oa[1], oa[2], oa[3]);
}

// ============================================================================
// K3a: split-K output projection partials.
// grid (8 row-tiles, 4 h-tiles, 8 splits), 256 threads.
// Tile: 64 rows x 32 h, K-chunk = 128 per split, BK=16 -> 8 iterations.
// Bs rows 144B (16B multiple) for aligned float4 reads.
// ============================================================================
__global__ void __launch_bounds__(256) outproj_split_kernel(
    const float* __restrict__ Wo)
{
    __shared__ float As[16][65];   // [j][row] (scalar-read only)
    __shared__ float Bs[16][36];   // [j][h]   (float4-read, 16B-aligned rows)
    int r0 = blockIdx.x * 64;
    int h0 = blockIdx.y * 32;
    int split = blockIdx.z;
    int j0base = split * (NH_*D_ / NSPLIT);   // 128-wide K chunk
    int tid = threadIdx.x;          // 256
    int ry = tid >> 3;              // 0..31 -> row pair
    int tx = tid & 7;               // -> h group of 4
    const float* Cc = g_CONCAT;
    float acc[2][4] = {};

    int arow = tid >> 2;            // 0..63 (A staging row)
    int ajq  = (tid & 3) * 4;       // j offset 0,4,8,12
    int bhr  = (tid & 127) >> 2;    // 0..31 (B staging h), threads 0..127 only
    int bjq  = (tid & 3) * 4;

    #pragma unroll
    for (int jc = 0; jc < 8; ++jc) {
        int j0 = j0base + jc * 16;
        __syncthreads();
        {
            float4 a = *(const float4*)(Cc + (r0+arow)*(NH_*D_) + j0 + ajq);
            As[ajq+0][arow] = a.x; As[ajq+1][arow] = a.y;
            As[ajq+2][arow] = a.z; As[ajq+3][arow] = a.w;
        }
        if (tid < 128) {
            float4 w = *(const float4*)(Wo + (h0+bhr)*(NH_*D_) + j0 + bjq);
            Bs[bjq+0][bhr] = w.x; Bs[bjq+1][bhr] = w.y;
            Bs[bjq+2][bhr] = w.z; Bs[bjq+3][bhr] = w.w;
        }
        __syncthreads();
        #pragma unroll
        for (int jj = 0; jj < 16; ++jj) {
            float a0 = As[jj][ry*2+0];
            float a1 = As[jj][ry*2+1];
            float4 b4 = *(const float4*)&Bs[jj][tx*4];
            float bv[4] = {b4.x, b4.y, b4.z, b4.w};
            #pragma unroll
            for (int j = 0; j < 4; ++j) {
                acc[0][j] = fmaf(a0, bv[j], acc[0][j]);
                acc[1][j] = fmaf(a1, bv[j], acc[1][j]);
            }
        }
    }
    float* Pp = g_PART + ((split*(B_*LQ_)) + r0 + ry*2)*H_ + h0 + tx*4;
    #pragma unroll
    for (int i = 0; i < 2; ++i)
        *(float4*)(Pp + i*H_) = make_float4(acc[i][0], acc[i][1], acc[i][2], acc[i][3]);
}

// ============================================================================
// K3b: reduce splits + bias.  out[r][h] = bias[h] + sum_s partial[s][r][h]
// ============================================================================
__global__ void __launch_bounds__(256) outproj_reduce_kernel(
    const float* __restrict__ bias, float* __restrict__ out)
{
    int idx = blockIdx.x * 256 + threadIdx.x;     // float4 index over 512*128/4
    int h4 = (idx & (H_/4 - 1)) * 4;
    float4 a = *(const float4*)(bias + h4);
    #pragma unroll
    for (int s = 0; s < NSPLIT; ++s) {
        float4 p = *(const float4*)(g_PART + s*(B_*LQ_*H_) + idx*4);
        a.x += p.x; a.y += p.y; a.z += p.z; a.w += p.w;
    }
    *(float4*)((float*)out + idx*4) = a;
}

// ============================================================================
extern "C" void kernel_launch(void* const* d_in, const int* in_sizes, int n_in,
                              void* d_out, int out_size)
{
    const float* queries    = (const float*)d_in[0];
    const float* keys       = (const float*)d_in[1];
    const float* values     = (const float*)d_in[2];
    const int*   valid_lens = (const int*)  d_in[3];
    const float* Wq         = (const float*)d_in[4];
    const float* Wk         = (const float*)d_in[5];
    const float* wv         = (const float*)d_in[6];
    const float* Wo_w       = (const float*)d_in[7];
    const float* Wo_b       = (const float*)d_in[8];
    float* out = (float*)d_out;

    kproj_kernel<<<dim3(4, 2, 32), 256>>>(keys, Wk);
    score_av_kernel<<<dim3(LQ_/8, NH_, B_), 256>>>(queries, Wq, wv, valid_lens, values);
    outproj_split_kernel<<<dim3(8, 4, NSPLIT), 256>>>(Wo_w);
    outproj_reduce_kernel<<<dim3(B_*LQ_*H_/4/256), 256>>>(Wo_b, out);
}